// round 13
// baseline (speedup 1.0000x reference)
#include <cuda_runtime.h>
#include <cuda_bf16.h>
#include <cstdint>

// Problem constants
#define BATCH 4096
#define TT    120
#define II    64
#define HH    128
#define G3    384   // 3*H

// 755MB fp32 scratch for precomputed input gates, layout [T][B][3H]
__device__ float g_xg[(size_t)TT * BATCH * G3];

__device__ __forceinline__ float sigf(float v) {
    return __fdividef(1.0f, 1.0f + __expf(-v));
}
__device__ __forceinline__ float tanhf_fast(float v) {
    return __fdividef(2.0f, 1.0f + __expf(-2.0f * v)) - 1.0f;
}

// ---------------- tensor-core helpers ----------------
__device__ __forceinline__ uint32_t s2u(const void* p) {
    return (uint32_t)__cvta_generic_to_shared(p);
}
__device__ __forceinline__ void ldsm_x4(uint32_t a[4], uint32_t addr) {
    asm volatile("ldmatrix.sync.aligned.m8n8.x4.shared.b16 {%0,%1,%2,%3}, [%4];"
                 : "=r"(a[0]), "=r"(a[1]), "=r"(a[2]), "=r"(a[3]) : "r"(addr));
}
__device__ __forceinline__ void ldsm_x2(uint32_t b[2], uint32_t addr) {
    asm volatile("ldmatrix.sync.aligned.m8n8.x2.shared.b16 {%0,%1}, [%2];"
                 : "=r"(b[0]), "=r"(b[1]) : "r"(addr));
}
__device__ __forceinline__ void mma16816(float c[4], const uint32_t a[4],
                                         const uint32_t b[2]) {
    asm volatile(
        "mma.sync.aligned.m16n8k16.row.col.f32.bf16.bf16.f32 "
        "{%0,%1,%2,%3}, {%4,%5,%6,%7}, {%8,%9}, {%0,%1,%2,%3};"
        : "+f"(c[0]), "+f"(c[1]), "+f"(c[2]), "+f"(c[3])
        : "r"(a[0]), "r"(a[1]), "r"(a[2]), "r"(a[3]), "r"(b[0]), "r"(b[1]));
}
__device__ __forceinline__ uint32_t cvt_bf16x2(float lo_elem, float hi_elem) {
    uint32_t d;
    asm("cvt.rn.bf16x2.f32 %0, %1, %2;" : "=r"(d) : "f"(hi_elem), "f"(lo_elem));
    return d;
}
__device__ __forceinline__ uint32_t pack_bf16x2(__nv_bfloat16 a, __nv_bfloat16 b) {
    uint32_t d;
    asm("mov.b32 %0, {%1, %2};" : "=r"(d)
        : "h"(*(const unsigned short*)&a), "h"(*(const unsigned short*)&b));
    return d;
}

// =====================================================================
// Kernel 1: x_gates via tensor cores (unchanged — ~262us)
// =====================================================================
#define XW   72
#define NT2  (TT * (BATCH / 64))
#define XP2_SMEM_BYTES ((G3 * XW * 2 + 64 * XW * 2) * 2)   // 129024

__global__ void __launch_bounds__(512, 1)
xproj_mma_kernel(const float* __restrict__ x,
                 const float* __restrict__ Wih,
                 const float* __restrict__ bih)
{
    extern __shared__ __align__(16) char smemc[];
    __nv_bfloat16* Whi = reinterpret_cast<__nv_bfloat16*>(smemc);
    __nv_bfloat16* Wlo = Whi + G3 * XW;
    __nv_bfloat16* Xhi = Wlo + G3 * XW;
    __nv_bfloat16* Xlo = Xhi + 64 * XW;

    const int tid   = threadIdx.x;
    const int w     = tid >> 5;
    const int lane  = tid & 31;
    const int g8    = lane >> 2;
    const int cc    = lane & 3;
    const int jbase = w * 8;
    const int j0    = jbase + 2 * cc;

    for (int i = tid; i < G3 * II; i += 512) {
        int n = i >> 6, k = i & 63;
        float v = Wih[i];
        __nv_bfloat16 hi = __float2bfloat16(v);
        Whi[n * XW + k] = hi;
        Wlo[n * XW + k] = __float2bfloat16(v - __bfloat162float(hi));
    }

    const float bR0 = bih[j0],       bR1 = bih[j0 + 1];
    const float bZ0 = bih[128 + j0], bZ1 = bih[128 + j0 + 1];
    const float bN0 = bih[256 + j0], bN1 = bih[256 + j0 + 1];

    const int arow = lane & 15;
    const int acol = (lane >> 4) * 8;
    uint32_t aHi[4], aLo[4];
#pragma unroll
    for (int mt = 0; mt < 4; ++mt) {
        aHi[mt] = s2u(Xhi + (mt * 16 + arow) * XW + acol);
        aLo[mt] = s2u(Xlo + (mt * 16 + arow) * XW + acol);
    }
    const int l16  = lane & 15;
    const int brow = l16 & 7;
    const int bkh  = (l16 >> 3) & 1;
    uint32_t bHi[3], bLo[3];
#pragma unroll
    for (int g = 0; g < 3; ++g) {
        int nb = g * 128 + jbase;
        bHi[g] = s2u(Whi + (nb + brow) * XW + 8 * bkh);
        bLo[g] = s2u(Wlo + (nb + brow) * XW + 8 * bkh);
    }

    const int xrow = tid >> 3;
    const int xcol = (tid & 7) * 8;
    float4 pa, pb;

    int tile = blockIdx.x;
    if (tile < NT2) {
        int t = tile % TT, b0 = (tile / TT) << 6;
        const float4* p = reinterpret_cast<const float4*>(
            x + ((size_t)(b0 + xrow) * TT + t) * II + xcol);
        pa = p[0]; pb = p[1];
    }

    for (; tile < NT2; tile += 148) {
        const int t  = tile % TT;
        const int b0 = (tile / TT) << 6;

        __syncthreads();

        {
            float v[8] = {pa.x, pa.y, pa.z, pa.w, pb.x, pb.y, pb.z, pb.w};
            __nv_bfloat16* hp = Xhi + xrow * XW + xcol;
            __nv_bfloat16* lp = Xlo + xrow * XW + xcol;
#pragma unroll
            for (int e = 0; e < 4; ++e) {
                float a0 = v[2 * e], a1 = v[2 * e + 1];
                __nv_bfloat16 h0 = __float2bfloat16(a0);
                __nv_bfloat16 h1 = __float2bfloat16(a1);
                *reinterpret_cast<uint32_t*>(hp + 2 * e) = pack_bf16x2(h0, h1);
                *reinterpret_cast<uint32_t*>(lp + 2 * e) =
                    cvt_bf16x2(a0 - __bfloat162float(h0), a1 - __bfloat162float(h1));
            }
        }

        {
            int nxt = tile + 148;
            if (nxt < NT2) {
                int tn = nxt % TT, bn = (nxt / TT) << 6;
                const float4* p = reinterpret_cast<const float4*>(
                    x + ((size_t)(bn + xrow) * TT + tn) * II + xcol);
                pa = p[0]; pb = p[1];
            }
        }

        __syncthreads();

        float C[4][3][4];
#pragma unroll
        for (int mt = 0; mt < 4; ++mt)
#pragma unroll
            for (int g = 0; g < 3; ++g)
#pragma unroll
                for (int e = 0; e < 4; ++e) C[mt][g][e] = 0.0f;

#pragma unroll
        for (int c8 = 0; c8 < 4; ++c8) {
            const uint32_t off = c8 * 32;
            uint32_t ahi[4][4], alo[4][4];
#pragma unroll
            for (int mt = 0; mt < 4; ++mt) {
                ldsm_x4(ahi[mt], aHi[mt] + off);
                ldsm_x4(alo[mt], aLo[mt] + off);
            }
#pragma unroll
            for (int g = 0; g < 3; ++g) {
                uint32_t bh[2], bl_[2];
                ldsm_x2(bh,  bHi[g] + off);
                ldsm_x2(bl_, bLo[g] + off);
#pragma unroll
                for (int mt = 0; mt < 4; ++mt) {
                    mma16816(C[mt][g], ahi[mt], bh);
                    mma16816(C[mt][g], alo[mt], bh);
                    mma16816(C[mt][g], ahi[mt], bl_);
                }
            }
        }

#pragma unroll
        for (int mt = 0; mt < 4; ++mt) {
#pragma unroll
            for (int rp = 0; rp < 2; ++rp) {
                int row = mt * 16 + g8 + rp * 8;
                float* dst = g_xg + ((size_t)t * BATCH + b0 + row) * G3 + j0;
                float2 o;
                o.x = C[mt][0][rp * 2] + bR0; o.y = C[mt][0][rp * 2 + 1] + bR1;
                *reinterpret_cast<float2*>(dst) = o;
                o.x = C[mt][1][rp * 2] + bZ0; o.y = C[mt][1][rp * 2 + 1] + bZ1;
                *reinterpret_cast<float2*>(dst + 128) = o;
                o.x = C[mt][2][rp * 2] + bN0; o.y = C[mt][2][rp * 2 + 1] + bN1;
                *reinterpret_cast<float2*>(dst + 256) = o;
            }
        }
    }
}

// =====================================================================
// Kernel 2: GRU recurrence — software-pipelined two independent chains
// (rows 0-15 = A, 16-31 = B) with double-buffered H planes.
//   stream: mma(B,t); epi(A,t); bar; mma(A,t+1); epi(B,t); bar
// Each epilogue's MUFUs overlap the tensor queue of the chain just
// issued (same-warp overlap). 2 barriers/step.
// W: unpadded 256B rows + XOR granule swizzle (conflict-free ldsm).
// H: [group][buf] hi/lo planes, 16x136 each (padded, linear).
// SMEM = 2*49152*2 + 8*2176*2 = 231424 B.
// =====================================================================
#define WSZ (G3 * HH)        // 49152 elems per W plane
#define HP  136
#define HSZ (16 * HP)        // 2176 elems per (group,buf) plane
#define R_SMEM_BYTES ((2 * WSZ + 8 * HSZ) * 2)   // 231424

__device__ __forceinline__ void mma_group(
    float C[3][4], uint32_t aHiAddr, uint32_t aLoAddr,
    const uint32_t bHiRow[3], const uint32_t bLoRow[3],
    uint32_t l3, uint32_t brow)
{
#pragma unroll
    for (int g = 0; g < 3; ++g)
#pragma unroll
        for (int e = 0; e < 4; ++e) C[g][e] = 0.0f;

#pragma unroll
    for (int cp = 0; cp < 4; ++cp) {
        uint32_t ah0[4], al0[4], ah1[4], al1[4];
        ldsm_x4(ah0, aHiAddr + cp * 64);
        ldsm_x4(ah1, aHiAddr + cp * 64 + 32);
        ldsm_x4(al0, aLoAddr + cp * 64);
        ldsm_x4(al1, aLoAddr + cp * 64 + 32);
        const uint32_t xoff = (((cp * 4 + l3) ^ brow) << 4);
#pragma unroll
        for (int g = 0; g < 3; ++g) {
            uint32_t bh[4], bl[4];
            ldsm_x4(bh, bHiRow[g] + xoff);
            ldsm_x4(bl, bLoRow[g] + xoff);
            mma16816(C[g], ah0, bh);       // chunk 2cp   (regs 0,1)
            mma16816(C[g], al0, bh);
            mma16816(C[g], ah0, bl);
            mma16816(C[g], ah1, bh + 2);   // chunk 2cp+1 (regs 2,3)
            mma16816(C[g], al1, bh + 2);
            mma16816(C[g], ah1, bl + 2);
        }
    }
}

__global__ void __launch_bounds__(512, 1)
gru_mma_kernel(const float* __restrict__ Whh,
               const float* __restrict__ bhh,
               float* __restrict__ out,
               int write_hT)
{
    extern __shared__ __align__(16) char smemc[];
    __nv_bfloat16* Whi = reinterpret_cast<__nv_bfloat16*>(smemc);
    __nv_bfloat16* Wlo = Whi + WSZ;
    __nv_bfloat16* Hhi = Wlo + WSZ;           // 4 planes: (g,buf)
    __nv_bfloat16* Hlo = Hhi + 4 * HSZ;       // 4 planes

    const int tid   = threadIdx.x;
    const int w     = tid >> 5;          // 0..15
    const int lane  = tid & 31;
    const int jbase = w * 8;
    const int g8    = lane >> 2;
    const int cc    = lane & 3;
    const int j0    = jbase + 2 * cc;
    const int b0    = blockIdx.x * 32;

    // ---- W planes: swizzled store (granule ^= row&7) ----
    for (int i = tid; i < WSZ; i += 512) {
        int n = i >> 7, k = i & 127;
        float v = Whh[i];
        __nv_bfloat16 hi = __float2bfloat16(v);
        int phys = (n << 7) + ((((k >> 3) ^ (n & 7)) << 3) | (k & 7));
        Whi[phys] = hi;
        Wlo[phys] = __float2bfloat16(v - __bfloat162float(hi));
    }
    // ---- zero all H planes ----
    for (int i = tid; i < 8 * HSZ; i += 512)
        Hhi[i] = __float2bfloat16(0.0f);   // covers Hhi+Hlo (contiguous)

    const float bR0 = bhh[j0],       bR1 = bhh[j0 + 1];
    const float bZ0 = bhh[128 + j0], bZ1 = bhh[128 + j0 + 1];
    const float bN0 = bhh[256 + j0], bN1 = bhh[256 + j0 + 1];

    __syncthreads();

    // ---- A-frag addresses: [group][buf] ----
    const int arow = lane & 15;
    const int acol = (lane >> 4) * 8;
    uint32_t aHi[2][2], aLo[2][2];
#pragma unroll
    for (int g = 0; g < 2; ++g)
#pragma unroll
        for (int bf = 0; bf < 2; ++bf) {
            int off = (g * 2 + bf) * HSZ + arow * HP + acol;
            aHi[g][bf] = s2u(Hhi + off);
            aLo[g][bf] = s2u(Hlo + off);
        }

    // ---- B-frag row bases (swizzled W) ----
    const uint32_t brow = lane & 7;
    const uint32_t l3   = (lane >> 3) & 3;   // matrix index in x4
    uint32_t bHiRow[3], bLoRow[3];
#pragma unroll
    for (int g = 0; g < 3; ++g) {
        int row = g * 128 + jbase + (int)brow;
        bHiRow[g] = s2u(Whi) + row * 256;
        bLoRow[g] = s2u(Wlo) + row * 256;
    }

    float holdA[2][2], holdB[2][2];
#pragma unroll
    for (int rp = 0; rp < 2; ++rp) {
        holdA[rp][0] = holdA[rp][1] = 0.0f;
        holdB[rp][0] = holdB[rp][1] = 0.0f;
    }

    // ---- prologue: xgA(0), mma(A,0) ----
    float2 XAr[2], XAz[2], XAn[2];
#pragma unroll
    for (int rp = 0; rp < 2; ++rp) {
        const float* rowp = g_xg + ((size_t)(b0 + g8 + rp * 8)) * G3 + j0;
        XAr[rp] = *reinterpret_cast<const float2*>(rowp);
        XAz[rp] = *reinterpret_cast<const float2*>(rowp + 128);
        XAn[rp] = *reinterpret_cast<const float2*>(rowp + 256);
    }
    float CA[3][4];
    mma_group(CA, aHi[0][0], aLo[0][0], bHiRow, bLoRow, l3, brow);

    for (int t = 0; t < TT; ++t) {
        const int buf  = t & 1;
        const int nbuf = buf ^ 1;

        // ---- xgB(t) ----
        float2 XBr[2], XBz[2], XBn[2];
#pragma unroll
        for (int rp = 0; rp < 2; ++rp) {
            const float* rowp =
                g_xg + ((size_t)t * BATCH + b0 + 16 + g8 + rp * 8) * G3 + j0;
            XBr[rp] = *reinterpret_cast<const float2*>(rowp);
            XBz[rp] = *reinterpret_cast<const float2*>(rowp + 128);
            XBn[rp] = *reinterpret_cast<const float2*>(rowp + 256);
        }

        // ---- mma(B, t) ----
        float CB[3][4];
        mma_group(CB, aHi[1][buf], aLo[1][buf], bHiRow, bLoRow, l3, brow);

        // ---- epi(A, t): overlaps B's tensor queue ----
#pragma unroll
        for (int rp = 0; rp < 2; ++rp) {
            const int lrow = g8 + rp * 8;
            float r0 = sigf(XAr[rp].x + CA[0][rp * 2]     + bR0);
            float r1 = sigf(XAr[rp].y + CA[0][rp * 2 + 1] + bR1);
            float z0 = sigf(XAz[rp].x + CA[1][rp * 2]     + bZ0);
            float z1 = sigf(XAz[rp].y + CA[1][rp * 2 + 1] + bZ1);
            float n0 = tanhf_fast(XAn[rp].x + r0 * (CA[2][rp * 2]     + bN0));
            float n1 = tanhf_fast(XAn[rp].y + r1 * (CA[2][rp * 2 + 1] + bN1));
            float h0 = n0 + z0 * (holdA[rp][0] - n0);
            float h1 = n1 + z1 * (holdA[rp][1] - n1);
            holdA[rp][0] = h0; holdA[rp][1] = h1;

            __nv_bfloat16 h0h = __float2bfloat16(h0);
            __nv_bfloat16 h1h = __float2bfloat16(h1);
            int doff = (0 * 2 + nbuf) * HSZ + lrow * HP + j0;
            *reinterpret_cast<uint32_t*>(Hhi + doff) = pack_bf16x2(h0h, h1h);
            *reinterpret_cast<uint32_t*>(Hlo + doff) =
                cvt_bf16x2(h0 - __bfloat162float(h0h),
                           h1 - __bfloat162float(h1h));
            *reinterpret_cast<float2*>(
                &out[((size_t)(b0 + lrow) * TT + t) * HH + j0]) =
                make_float2(h0, h1);
        }

        __syncthreads();   // HA[nbuf] writes visible

        // ---- xgA(t+1) + mma(A, t+1) ----
        if (t + 1 < TT) {
#pragma unroll
            for (int rp = 0; rp < 2; ++rp) {
                const float* rowp =
                    g_xg + ((size_t)(t + 1) * BATCH + b0 + g8 + rp * 8) * G3 + j0;
                XAr[rp] = *reinterpret_cast<const float2*>(rowp);
                XAz[rp] = *reinterpret_cast<const float2*>(rowp + 128);
                XAn[rp] = *reinterpret_cast<const float2*>(rowp + 256);
            }
            mma_group(CA, aHi[0][nbuf], aLo[0][nbuf], bHiRow, bLoRow, l3, brow);
        }

        // ---- epi(B, t): overlaps A's tensor queue ----
#pragma unroll
        for (int rp = 0; rp < 2; ++rp) {
            const int lrow = g8 + rp * 8;
            float r0 = sigf(XBr[rp].x + CB[0][rp * 2]     + bR0);
            float r1 = sigf(XBr[rp].y + CB[0][rp * 2 + 1] + bR1);
            float z0 = sigf(XBz[rp].x + CB[1][rp * 2]     + bZ0);
            float z1 = sigf(XBz[rp].y + CB[1][rp * 2 + 1] + bZ1);
            float n0 = tanhf_fast(XBn[rp].x + r0 * (CB[2][rp * 2]     + bN0));
            float n1 = tanhf_fast(XBn[rp].y + r1 * (CB[2][rp * 2 + 1] + bN1));
            float h0 = n0 + z0 * (holdB[rp][0] - n0);
            float h1 = n1 + z1 * (holdB[rp][1] - n1);
            holdB[rp][0] = h0; holdB[rp][1] = h1;

            __nv_bfloat16 h0h = __float2bfloat16(h0);
            __nv_bfloat16 h1h = __float2bfloat16(h1);
            int doff = (1 * 2 + nbuf) * HSZ + lrow * HP + j0;
            *reinterpret_cast<uint32_t*>(Hhi + doff) = pack_bf16x2(h0h, h1h);
            *reinterpret_cast<uint32_t*>(Hlo + doff) =
                cvt_bf16x2(h0 - __bfloat162float(h0h),
                           h1 - __bfloat162float(h1h));
            *reinterpret_cast<float2*>(
                &out[((size_t)(b0 + 16 + lrow) * TT + t) * HH + j0]) =
                make_float2(h0, h1);
        }

        __syncthreads();   // HB[nbuf] writes visible
    }

    if (write_hT) {
        float* outF = out + (size_t)BATCH * TT * HH;
#pragma unroll
        for (int rp = 0; rp < 2; ++rp) {
            int lrow = g8 + rp * 8;
            *reinterpret_cast<float2*>(&outF[(size_t)(b0 + lrow) * HH + j0]) =
                make_float2(holdA[rp][0], holdA[rp][1]);
            *reinterpret_cast<float2*>(&outF[(size_t)(b0 + 16 + lrow) * HH + j0]) =
                make_float2(holdB[rp][0], holdB[rp][1]);
        }
    }
}

// =====================================================================
extern "C" void kernel_launch(void* const* d_in, const int* in_sizes, int n_in,
                              void* d_out, int out_size)
{
    const float* x   = (const float*)d_in[0];
    const float* Wih = (const float*)d_in[1];
    const float* Whh = (const float*)d_in[2];
    const float* bih = (const float*)d_in[3];
    const float* bhh = (const float*)d_in[4];
    float* out = (float*)d_out;
    (void)in_sizes; (void)n_in;

    cudaFuncSetAttribute(xproj_mma_kernel,
                         cudaFuncAttributeMaxDynamicSharedMemorySize, XP2_SMEM_BYTES);
    cudaFuncSetAttribute(gru_mma_kernel,
                         cudaFuncAttributeMaxDynamicSharedMemorySize, R_SMEM_BYTES);

    int write_hT = (out_size >= BATCH * TT * HH + BATCH * HH) ? 1 : 0;

    xproj_mma_kernel<<<148, 512, XP2_SMEM_BYTES>>>(x, Wih, bih);
    gru_mma_kernel<<<BATCH / 32, 512, R_SMEM_BYTES>>>(Whh, bhh, out, write_hT);
}